// round 15
// baseline (speedup 1.0000x reference)
#include <cuda_runtime.h>
#include <math.h>
#include <stdint.h>

#define POOLK 7
#define HH 50
#define WW 50
#define CC 512
#define NROIS 300
#define NPOS (HH * WW)
#define NTASK (NROIS * POOLK)   // 2100 (roi,ph) block-tasks
#define GRIDB 888               // 6 blocks/SM, co-residency proven (R8 ran this)

// Device-global scratch (no allocations allowed).
__device__ float g_part[2 * NPOS];      // per-position partial maxima (float2)
__device__ unsigned long long g_sync;   // monotonic grid-sync ticket (never reset)

__global__ void __launch_bounds__(256, 8)
fused_kernel(const float* __restrict__ fm, const float* __restrict__ rois,
             float* __restrict__ out) {
    const int tid = threadIdx.x;
    const int wid = tid >> 5;
    const int lane = tid & 31;
    const int gw = blockIdx.x * 8 + wid;   // global warp id, 0..7103

    // ---- Phase A: partial channel maxima, 2 warps per position ------------
    // Warp (pos, half) reduces 256 channels: 2 x float4 per lane.
    {
        const int pos = gw >> 1;
        const int half = gw & 1;
        if (pos < NPOS) {
            const float4* p = reinterpret_cast<const float4*>(fm + (size_t)pos * CC)
                              + half * 64;
            const float4 a = p[lane];
            const float4 b = p[lane + 32];
            float m = fmaxf(fmaxf(fmaxf(a.x, a.y), fmaxf(a.z, a.w)),
                            fmaxf(fmaxf(b.x, b.y), fmaxf(b.z, b.w)));
#pragma unroll
            for (int o = 16; o; o >>= 1)
                m = fmaxf(m, __shfl_xor_sync(0xffffffffu, m, o));
            if (lane == 0) g_part[pos * 2 + half] = m;
        }
    }

    // ---- Grid-wide sync (monotonic ticket; nanosleep backoff) -------------
    __syncthreads();
    if (tid == 0) {
        __threadfence();  // publish this block's g_part stores
        unsigned long long old = atomicAdd(&g_sync, 1ULL);
        unsigned long long target = (old / GRIDB + 1ULL) * GRIDB;
        unsigned long long v;
        for (;;) {
            asm volatile("ld.acquire.gpu.u64 %0, [%1];"
                         : "=l"(v) : "l"(&g_sync) : "memory");
            if (v >= target) break;
            __nanosleep(40);
        }
    }
    __syncthreads();

    // ---- Phase B/C: R4 roi body, grid-strided over 2100 (roi,ph) tasks ----
    __shared__ float sbin[POOLK];

    for (int task = blockIdx.x; task < NTASK; task += GRIDB) {
        const int roi = task / POOLK;
        const int ph = task - roi * POOLK;

        const float* r = rois + roi * 5;
        // truncation matches astype(int32) for nonneg; *0.0625f exact (== /16)
        const int x1 = (int)(__ldg(r + 1) * 0.0625f);
        const int y1 = (int)(__ldg(r + 2) * 0.0625f);
        const int x2 = (int)(__ldg(r + 3) * 0.0625f);
        const int y2 = (int)(__ldg(r + 4) * 0.0625f);
        const int rh = y2 - y1 + 1;
        const int rw = x2 - x1 + 1;

        const int hs = min(max(y1 + (ph * rh) / POOLK, 0), HH);
        const int he = min(max(y1 + ((ph + 1) * rh + POOLK - 1) / POOLK, 0), HH);

        if (wid < POOLK) {
            const int pw = wid;
            const int ws = min(max(x1 + (pw * rw) / POOLK, 0), WW);
            const int we = min(max(x1 + ((pw + 1) * rw + POOLK - 1) / POOLK, 0), WW);
            const int nh = he - hs;
            const int nw = we - ws;
            const int cnt = (nh > 0 && nw > 0) ? nh * nw : 0;
            float m = -INFINITY;
            for (int e = lane; e < cnt; e += 32) {
                const int dh = e / nw;
                const int dw = e - dh * nw;
                const float2 v = __ldg(reinterpret_cast<const float2*>(g_part)
                                       + (hs + dh) * WW + (ws + dw));
                m = fmaxf(m, fmaxf(v.x, v.y));
            }
#pragma unroll
            for (int o = 16; o; o >>= 1)
                m = fmaxf(m, __shfl_xor_sync(0xffffffffu, m, o));
            if (lane == 0) sbin[pw] = m;
        }
        __syncthreads();

        // Write 7 bins * 512 ch = 896 float4, coalesced; paced loop (low
        // MLP_p1 -> no cross-CTA L1tex-queue blowup; R4-proven shape).
        float4* o4 = reinterpret_cast<float4*>(out) + (size_t)task * POOLK * (CC / 4);
        const int n4 = POOLK * (CC / 4);  // 896
        for (int idx = tid; idx < n4; idx += 256) {
            const float v = sbin[idx >> 7];
            o4[idx] = make_float4(v, v, v, v);
        }
        __syncthreads();  // protect sbin before next task iteration
    }
}

extern "C" void kernel_launch(void* const* d_in, const int* in_sizes, int n_in,
                              void* d_out, int out_size) {
    const float* rois = (const float*)d_in[0];
    const float* fm = (const float*)d_in[1];
    if (n_in >= 2 && in_sizes[0] > in_sizes[1]) {
        rois = (const float*)d_in[1];
        fm = (const float*)d_in[0];
    }
    float* out = (float*)d_out;

    fused_kernel<<<GRIDB, 256>>>(fm, rois, out);
}